// round 16
// baseline (speedup 1.0000x reference)
#include <cuda_runtime.h>
#include <cuda_bf16.h>
#include <cstdint>
#include <math.h>

#define T_SEQ   256
#define BATCH   16
#define NINP    400
#define NHID    1150
#define VOCABP1 33279
#define M_TOK   (BATCH * T_SEQ)   // 4096

#define KP_400  448
#define KP_1150 1152

// ---------------- scratch (static device globals; no allocation) ----------------
__device__ float g_xg[(size_t)M_TOK * 4 * NHID];           // gate preactivations
__device__ __nv_bfloat16 g_hb[2][16 * 1160];               // h ping-pong, [b][u], SH stride
__device__ unsigned g_bar;

__device__ __nv_bfloat16 g_ab0[(size_t)M_TOK * KP_400];
__device__ __nv_bfloat16 g_ab1[(size_t)M_TOK * KP_1150];
__device__ __nv_bfloat16 g_ab2[(size_t)M_TOK * KP_1150];
__device__ __nv_bfloat16 g_ab3[(size_t)M_TOK * KP_400];
__device__ __nv_bfloat16 g_w0t[(size_t)4600 * KP_400];
__device__ __nv_bfloat16 g_w1t[(size_t)4600 * KP_1150];
__device__ __nv_bfloat16 g_w2t[(size_t)1600 * KP_1150];
__device__ __nv_bfloat16 g_embb[(size_t)VOCABP1 * KP_400];

// ---------------- helpers ----------------
__device__ __forceinline__ uint32_t smem_to_u32(const void* p) {
    uint32_t a;
    asm("{ .reg .u64 t; cvta.to.shared.u64 t, %1; cvt.u32.u64 %0, t; }"
        : "=r"(a) : "l"(p));
    return a;
}
#define SMEM_SWIZZLE_128B(b) ((b) ^ (((b) >> 3) & 0x70))

#define MMA_BF16(d, a, b)                                                     \
    asm volatile("mma.sync.aligned.m16n8k16.row.col.f32.bf16.bf16.f32 "      \
                 "{%0,%1,%2,%3}, {%4,%5,%6,%7}, {%8,%9}, {%0,%1,%2,%3};"      \
                 : "+f"(d[0]), "+f"(d[1]), "+f"(d[2]), "+f"(d[3])             \
                 : "r"(a[0]), "r"(a[1]), "r"(a[2]), "r"(a[3]),                \
                   "r"(b[0]), "r"(b[1]))

// ---------------- grid barrier (monotonic across launches; prep resets) --------
__device__ __forceinline__ void grid_sync(unsigned target) {
    __syncthreads();
    if (threadIdx.x == 0) {
        __threadfence();
        atomicAdd(&g_bar, 1u);
        while (*(volatile unsigned*)&g_bar < target) {}
        __threadfence();
    }
    __syncthreads();
}

// ---------------- fused prep kernel (ONE launch; also resets g_bar) -------------
#define PREP_BLOCKS 9528

__device__ __forceinline__ void transpose_tile(
    const float* __restrict__ W, __nv_bfloat16* __restrict__ Wt,
    int K, int N, int Kpad, int bt, int nyb, float (*tile)[33])
{
    int n0 = (bt / nyb) * 32, k0 = (bt % nyb) * 32;
    int tx = threadIdx.x & 31, ty = threadIdx.x >> 5;
    for (int i = ty; i < 32; i += 8) {
        int k = k0 + i, n = n0 + tx;
        tile[i][tx] = (k < K && n < N) ? W[(size_t)k * N + n] : 0.f;
    }
    __syncthreads();
    for (int i = ty; i < 32; i += 8) {
        int n = n0 + i, k = k0 + tx;
        if (n < N && k < Kpad)
            Wt[(size_t)n * Kpad + k] = __float2bfloat16(tile[tx][i]);
    }
}

__global__ __launch_bounds__(256) void prep_k(
    const float* __restrict__ emb,
    const float* __restrict__ W0, const float* __restrict__ W1,
    const float* __restrict__ W2)
{
    __shared__ float tile[32][33];
    int b = blockIdx.x;
    if (b < 512) {
        const size_t tot = (size_t)VOCABP1 * KP_400;
        for (size_t idx = (size_t)b * 256 + threadIdx.x; idx < tot; idx += 512 * 256) {
            int r = (int)(idx / KP_400), c = (int)(idx % KP_400);
            g_embb[idx] = (c < NINP) ? __float2bfloat16(emb[(size_t)r * NINP + c])
                                     : __nv_bfloat16(0.f);
        }
    } else if (b < 2528) {
        transpose_tile(W0, g_w0t, NINP, 4 * NHID, KP_400, b - 512, 14, tile);
    } else if (b < 7712) {
        transpose_tile(W1, g_w1t, NHID, 4 * NHID, KP_1150, b - 2528, 36, tile);
    } else if (b < 9512) {
        transpose_tile(W2, g_w2t, NHID, 4 * NINP, KP_1150, b - 7712, 36, tile);
    } else {
        if (b == 9512 && threadIdx.x == 0) g_bar = 0u;   // barrier reset, once/replay
        int m = (b - 9512) * 256 + threadIdx.x;
        if (m < M_TOK) {
            g_ab1[(size_t)m * KP_1150 + 1150] = __nv_bfloat16(0.f);
            g_ab1[(size_t)m * KP_1150 + 1151] = __nv_bfloat16(0.f);
            g_ab2[(size_t)m * KP_1150 + 1150] = __nv_bfloat16(0.f);
            g_ab2[(size_t)m * KP_1150 + 1151] = __nv_bfloat16(0.f);
            for (int c = NINP; c < KP_400; c++)
                g_ab3[(size_t)m * KP_400 + c] = __nv_bfloat16(0.f);
        }
    }
}

// embedding gather in bf16
__global__ void embed_bf_k(const int* __restrict__ tok,
                           const __nv_bfloat16* __restrict__ embb,
                           __nv_bfloat16* __restrict__ x0) {
    int m = blockIdx.x;
    int t = tok[m];
    const uint4* src = (const uint4*)(embb + (size_t)t * KP_400);
    uint4* dst = (uint4*)(x0 + (size_t)m * KP_400);
    for (int i = threadIdx.x; i < KP_400 * 2 / 16; i += blockDim.x) dst[i] = src[i];
}

// ================= streaming bf16 GEMM (R13), 128x128 tile, 256 thr =============
#define GSTAGES 3
#define GEMM_SMEM (GSTAGES * 32768)

template<bool BIAS, int KTAIL>
__global__ __launch_bounds__(256, 2) void bf16_gemm_k(
    const __nv_bfloat16* __restrict__ A, const __nv_bfloat16* __restrict__ B,
    const float* __restrict__ bias, float* __restrict__ C,
    int M, int N, int Kpad)
{
    extern __shared__ char smem[];
    const uint32_t sbase = smem_to_u32(smem);

    const int tid  = threadIdx.x;
    const int wid  = tid >> 5;
    const int lane = tid & 31;
    const int bm   = blockIdx.y * 128;
    const int bn   = blockIdx.x * 128;
    const int wm   = (wid >> 2) * 64;
    const int wn   = (wid & 3) * 32;

    const int lrow  = tid >> 1;
    const int lhalf = tid & 1;
    const __nv_bfloat16* Asrc = A + (size_t)(bm + lrow) * Kpad + lhalf * 32;
    const int gnrow = bn + lrow;
    const __nv_bfloat16* Bsrc = B + (size_t)gnrow * Kpad + lhalf * 32;
    const int bvalid = (gnrow < N) ? 16 : 0;

    const int lm16 = lane & 15;
    const int lk16 = lane >> 4;
    const int ln8  = lane & 7;
    const int lkb  = (lane >> 3) & 1;

    float acc[4][4][4];
#pragma unroll
    for (int mf = 0; mf < 4; mf++)
#pragma unroll
        for (int nf = 0; nf < 4; nf++)
#pragma unroll
            for (int i = 0; i < 4; i++) acc[mf][nf][i] = 0.f;

    auto load_tile = [&](int stage, int kt) {
        uint32_t sa = sbase + stage * 32768;
        uint32_t sb = sa + 16384;
        const __nv_bfloat16* ap = Asrc + kt * 64;
        const __nv_bfloat16* bp = Bsrc + kt * 64;
#pragma unroll
        for (int j = 0; j < 4; j++) {
            uint32_t off = SMEM_SWIZZLE_128B((uint32_t)(lrow * 128 + lhalf * 64 + j * 16));
            asm volatile("cp.async.cg.shared.global [%0], [%1], 16;"
                         :: "r"(sa + off), "l"(ap + j * 8));
            asm volatile("cp.async.cg.shared.global [%0], [%1], 16, %2;"
                         :: "r"(sb + off), "l"(bp + j * 8), "r"(bvalid));
        }
    };

    const int nkt = Kpad >> 6;

#pragma unroll
    for (int s = 0; s < GSTAGES - 1; s++) {
        load_tile(s, s);
        asm volatile("cp.async.commit_group;" ::: "memory");
    }

    for (int kt = 0; kt < nkt; kt++) {
        asm volatile("cp.async.wait_group %0;" :: "n"(GSTAGES - 2) : "memory");
        __syncthreads();

        if (kt + GSTAGES - 1 < nkt) {
            load_tile((kt + GSTAGES - 1) % GSTAGES, kt + GSTAGES - 1);
            asm volatile("cp.async.commit_group;" ::: "memory");
        } else {
            asm volatile("cp.async.commit_group;" ::: "memory");
        }

        uint32_t sa = sbase + (kt % GSTAGES) * 32768;
        uint32_t sb = sa + 16384;
        const bool last = (kt == nkt - 1);
#pragma unroll
        for (int s = 0; s < 4; s++) {
            if (s >= KTAIL && last) break;
            uint32_t af[4][4], bfr[4][2];
#pragma unroll
            for (int mf = 0; mf < 4; mf++) {
                uint32_t off = (uint32_t)((wm + mf * 16 + lm16) * 128 + s * 32 + lk16 * 16);
                asm volatile("ldmatrix.sync.aligned.m8n8.x4.shared.b16 "
                             "{%0,%1,%2,%3}, [%4];"
                             : "=r"(af[mf][0]), "=r"(af[mf][1]),
                               "=r"(af[mf][2]), "=r"(af[mf][3])
                             : "r"(sa + SMEM_SWIZZLE_128B(off)));
            }
#pragma unroll
            for (int nf = 0; nf < 4; nf++) {
                uint32_t off = (uint32_t)((wn + nf * 8 + ln8) * 128 + s * 32 + lkb * 16);
                asm volatile("ldmatrix.sync.aligned.m8n8.x2.shared.b16 "
                             "{%0,%1}, [%2];"
                             : "=r"(bfr[nf][0]), "=r"(bfr[nf][1])
                             : "r"(sb + SMEM_SWIZZLE_128B(off)));
            }
#pragma unroll
            for (int mf = 0; mf < 4; mf++)
#pragma unroll
                for (int nf = 0; nf < 4; nf++)
                    MMA_BF16(acc[mf][nf], af[mf], bfr[nf]);
        }
    }

    const int gID = lane >> 2;
    const int tg  = lane & 3;
#pragma unroll
    for (int mf = 0; mf < 4; mf++) {
        int r0 = bm + wm + mf * 16 + gID;
#pragma unroll
        for (int nf = 0; nf < 4; nf++) {
            int c0 = bn + wn + nf * 8 + tg * 2;
            float b0v = 0.f, b1v = 0.f;
            if (BIAS) {
                if (c0 < N)     b0v = bias[c0];
                if (c0 + 1 < N) b1v = bias[c0 + 1];
            }
            if (c0 < N) {
                C[(size_t)r0 * N + c0]       = acc[mf][nf][0] + b0v;
                C[(size_t)(r0 + 8) * N + c0] = acc[mf][nf][2] + b0v;
            }
            if (c0 + 1 < N) {
                C[(size_t)r0 * N + c0 + 1]       = acc[mf][nf][1] + b1v;
                C[(size_t)(r0 + 8) * N + c0 + 1] = acc[mf][nf][3] + b1v;
            }
        }
    }
}

// ====== occupancy-probe decode GEMM: 512 threads, 16 warps, 128x128 tile ========
// Warp tile 32x32 (acc = 32 regs/thread, no spill). 4 warps/SMSP at 1 CTA/SM.
template<int KTAIL>
__global__ __launch_bounds__(512, 1) void bf16_gemm_512_k(
    const __nv_bfloat16* __restrict__ A, const __nv_bfloat16* __restrict__ B,
    float* __restrict__ C, int M, int N, int Kpad)
{
    extern __shared__ char smem[];
    const uint32_t sbase = smem_to_u32(smem);

    const int tid  = threadIdx.x;
    const int wid  = tid >> 5;           // 0..15
    const int lane = tid & 31;
    const int bm   = blockIdx.y * 128;
    const int bn   = blockIdx.x * 128;
    const int wm   = (wid >> 2) * 32;    // 0,32,64,96
    const int wn   = (wid & 3) * 32;     // 0,32,64,96

    // loads: 512 threads; thread -> (row, quarter), 2x 16B chunks
    const int lrow = tid >> 2;           // 0..127
    const int lq   = tid & 3;            // chunks 2lq, 2lq+1 (elems lq*16 .. +15)
    const __nv_bfloat16* Asrc = A + (size_t)(bm + lrow) * Kpad + lq * 16;
    const int gnrow = bn + lrow;
    const __nv_bfloat16* Bsrc = B + (size_t)gnrow * Kpad + lq * 16;
    const int bvalid = (gnrow < N) ? 16 : 0;

    const int lm16 = lane & 15;
    const int lk16 = lane >> 4;
    const int ln8  = lane & 7;
    const int lkb  = (lane >> 3) & 1;

    float acc[2][4][4];
#pragma unroll
    for (int mf = 0; mf < 2; mf++)
#pragma unroll
        for (int nf = 0; nf < 4; nf++)
#pragma unroll
            for (int i = 0; i < 4; i++) acc[mf][nf][i] = 0.f;

    auto load_tile = [&](int stage, int kt) {
        uint32_t sa = sbase + stage * 32768;
        uint32_t sb = sa + 16384;
        const __nv_bfloat16* ap = Asrc + kt * 64;
        const __nv_bfloat16* bp = Bsrc + kt * 64;
#pragma unroll
        for (int j = 0; j < 2; j++) {
            uint32_t off = SMEM_SWIZZLE_128B((uint32_t)(lrow * 128 + (lq * 2 + j) * 16));
            asm volatile("cp.async.cg.shared.global [%0], [%1], 16;"
                         :: "r"(sa + off), "l"(ap + j * 8));
            asm volatile("cp.async.cg.shared.global [%0], [%1], 16, %2;"
                         :: "r"(sb + off), "l"(bp + j * 8), "r"(bvalid));
        }
    };

    const int nkt = Kpad >> 6;

#pragma unroll
    for (int s = 0; s < GSTAGES - 1; s++) {
        load_tile(s, s);
        asm volatile("cp.async.commit_group;" ::: "memory");
    }

    for (int kt = 0; kt < nkt; kt++) {
        asm volatile("cp.async.wait_group %0;" :: "n"(GSTAGES - 2) : "memory");
        __syncthreads();

        if (kt + GSTAGES - 1 < nkt) {
            load_tile((kt + GSTAGES - 1) % GSTAGES, kt + GSTAGES - 1);
            asm volatile("cp.async.commit_group;" ::: "memory");
        } else {
            asm volatile("cp.async.commit_group;" ::: "memory");
        }

        uint32_t sa = sbase + (kt % GSTAGES) * 32768;
        uint32_t sb = sa + 16384;
        const bool last = (kt == nkt - 1);
#pragma unroll
        for (int s = 0; s < 4; s++) {
            if (s >= KTAIL && last) break;
            uint32_t af[2][4], bfr[4][2];
#pragma unroll
            for (int mf = 0; mf < 2; mf++) {
                uint32_t off = (uint32_t)((wm + mf * 16 + lm16) * 128 + s * 32 + lk16 * 16);
                asm volatile("ldmatrix.sync.aligned.m8n8.x4.shared.b16 "
                             "{%0,%1,%2,%3}, [%4];"
                             : "=r"(af[mf][0]), "=r"(af[mf][1]),
                               "=r"(af[mf][2]), "=r"(af[mf][3])
                             : "r"(sa + SMEM_SWIZZLE_128B(off)));
            }
#pragma unroll
            for (int nf = 0; nf < 4; nf++) {
                uint32_t off = (uint32_t)((wn + nf * 8 + ln8) * 128 + s * 32 + lkb * 16);
                asm volatile("ldmatrix.sync.aligned.m8n8.x2.shared.b16 "
                             "{%0,%1}, [%2];"
                             : "=r"(bfr[nf][0]), "=r"(bfr[nf][1])
                             : "r"(sb + SMEM_SWIZZLE_128B(off)));
            }
#pragma unroll
            for (int mf = 0; mf < 2; mf++)
#pragma unroll
                for (int nf = 0; nf < 4; nf++)
                    MMA_BF16(acc[mf][nf], af[mf], bfr[nf]);
        }
    }

    const int gID = lane >> 2;
    const int tg  = lane & 3;
#pragma unroll
    for (int mf = 0; mf < 2; mf++) {
        int r0 = bm + wm + mf * 16 + gID;
#pragma unroll
        for (int nf = 0; nf < 4; nf++) {
            int c0 = bn + wn + nf * 8 + tg * 2;
            if (c0 < N) {
                C[(size_t)r0 * N + c0]       = acc[mf][nf][0];
                C[(size_t)(r0 + 8) * N + c0] = acc[mf][nf][2];
            }
            if (c0 + 1 < N) {
                C[(size_t)r0 * N + c0 + 1]       = acc[mf][nf][1];
                C[(size_t)(r0 + 8) * N + c0 + 1] = acc[mf][nf][3];
            }
        }
    }
}

// ============== tensor-core persistent LSTM recurrence (bar_base arg) ===========
template<int U, int KPU, int NCTA>
__global__ __launch_bounds__(256) void lstm_tc_k(
    const float* __restrict__ Um,
    const float* __restrict__ xg,
    __nv_bfloat16* __restrict__ xout,
    int ostride, unsigned bar_base)
{
    constexpr int N4 = 4 * U;
    constexpr int KT = KPU / 16;
    constexpr int SH = KPU + 8;

    extern __shared__ char smraw[];
    const uint32_t ubase = smem_to_u32(smraw);
    const uint32_t hbase = ubase + 32 * SH * 2;
    float* red = (float*)(smraw + 32 * SH * 2 + 16 * SH * 2);
    float* gat = red + 512;
    __nv_bfloat16* U_s = (__nv_bfloat16*)smraw;

    const int tid  = threadIdx.x;
    const int wid  = tid >> 5;
    const int lane = tid & 31;
    const int nt   = wid & 3;
    const int kh   = wid >> 2;
    const int lm16 = lane & 15;
    const int lk16 = lane >> 4;
    const int ln8  = lane & 7;
    const int lkb  = (lane >> 3) & 1;
    const int gID  = lane >> 2;
    const int tg   = lane & 3;
    const int ub   = blockIdx.x * 8;

    for (int idx = tid; idx < 32 * KPU; idx += 256) {
        int k = idx >> 5, cc = idx & 31;
        int g = cc >> 3, ul = cc & 7;
        int uu = ub + ul;
        float v = (k < U && uu < U) ? Um[(size_t)k * N4 + (size_t)g * U + uu] : 0.f;
        U_s[cc * SH + k] = __float2bfloat16(v);
    }
    for (int idx = blockIdx.x * 256 + tid; idx < 2 * 16 * SH; idx += NCTA * 256)
        ((__nv_bfloat16*)g_hb)[idx] = __nv_bfloat16(0.f);

    float creg = 0.f;
    unsigned gen = 1;
    grid_sync(bar_base + gen * NCTA);

    const uint32_t aaddr0 = hbase + lm16 * (SH * 2) + lk16 * 16;
    const uint32_t baddr0 = ubase + (nt * 8 + ln8) * (SH * 2) + lkb * 16;

    for (int t = 0; t < T_SEQ; ++t) {
        {
            const char* src = (const char*)&g_hb[t & 1][0];
            for (int i = tid; i < 2 * SH; i += 256) {
                asm volatile("cp.async.cg.shared.global [%0], [%1], 16;"
                             :: "r"(hbase + i * 16), "l"(src + i * 16));
            }
            asm volatile("cp.async.commit_group;" ::: "memory");
            asm volatile("cp.async.wait_group 0;" ::: "memory");
            __syncthreads();
        }

        float accA[4] = {0.f, 0.f, 0.f, 0.f};
        float accB[4] = {0.f, 0.f, 0.f, 0.f};
#pragma unroll
        for (int kt = kh; kt < KT; kt += 2) {
            uint32_t a[4], b[2];
            asm volatile("ldmatrix.sync.aligned.m8n8.x4.shared.b16 "
                         "{%0,%1,%2,%3}, [%4];"
                         : "=r"(a[0]), "=r"(a[1]), "=r"(a[2]), "=r"(a[3])
                         : "r"(aaddr0 + kt * 32));
            asm volatile("ldmatrix.sync.aligned.m8n8.x2.shared.b16 "
                         "{%0,%1}, [%2];"
                         : "=r"(b[0]), "=r"(b[1])
                         : "r"(baddr0 + kt * 32));
            if ((kt >> 1) & 1) { MMA_BF16(accB, a, b); }
            else               { MMA_BF16(accA, a, b); }
        }
#pragma unroll
        for (int i = 0; i < 4; i++) accA[i] += accB[i];

        const int i00 = nt * 128 + gID * 8 + tg * 2;
        const int i10 = nt * 128 + (gID + 8) * 8 + tg * 2;
        if (kh == 1) {
            red[i00]     = accA[0];
            red[i00 + 1] = accA[1];
            red[i10]     = accA[2];
            red[i10 + 1] = accA[3];
        }
        __syncthreads();
        if (kh == 0) {
            accA[0] += red[i00];
            accA[1] += red[i00 + 1];
            accA[2] += red[i10];
            accA[3] += red[i10 + 1];
            const int uu0 = ub + tg * 2, uu1 = uu0 + 1;
            const float* xr0 = xg + ((size_t)gID * T_SEQ + t) * N4 + (size_t)nt * U;
            const float* xr1 = xg + ((size_t)(gID + 8) * T_SEQ + t) * N4 + (size_t)nt * U;
            if (uu0 < U) { accA[0] += __ldg(&xr0[uu0]); accA[2] += __ldg(&xr1[uu0]); }
            if (uu1 < U) { accA[1] += __ldg(&xr0[uu1]); accA[3] += __ldg(&xr1[uu1]); }
            gat[i00]     = accA[0];
            gat[i00 + 1] = accA[1];
            gat[i10]     = accA[2];
            gat[i10 + 1] = accA[3];
        }
        __syncthreads();

        if (tid < 128) {
            int b = tid >> 3, ul = tid & 7;
            int uu = ub + ul;
            float iv  = gat[0 * 128 + tid];
            float fv  = gat[1 * 128 + tid];
            float cgv = gat[2 * 128 + tid];
            float ov  = gat[3 * 128 + tid];
            iv = 1.f / (1.f + __expf(-iv));
            fv = 1.f / (1.f + __expf(-fv));
            ov = 1.f / (1.f + __expf(-ov));
            cgv = tanhf(cgv);
            creg = fv * creg + iv * cgv;
            float hv = ov * tanhf(creg);
            if (uu < U) {
                __nv_bfloat16 hb = __float2bfloat16(hv);
                g_hb[(t & 1) ^ 1][b * SH + uu] = hb;
                xout[((size_t)b * T_SEQ + t) * ostride + uu] = hb;
            }
            __threadfence();
        }
        gen++;
        grid_sync(bar_base + gen * NCTA);
    }
}

// ---------------- online row softmax (512 threads) ----------------
__global__ __launch_bounds__(512) void softmax_k(float* __restrict__ out, int N) {
    int m = blockIdx.x;
    float* row = out + (size_t)m * N;
    __shared__ float sm_[16], ss_[16];
    __shared__ float fm, fs;
    int tid = threadIdx.x, w = tid >> 5, ln = tid & 31;

    float mx = -3.4e38f, s = 0.f;
    for (int i = tid; i < N; i += 512) {
        float v = row[i];
        float nm = fmaxf(mx, v);
        s = s * __expf(mx - nm) + __expf(v - nm);
        mx = nm;
    }
#pragma unroll
    for (int o = 16; o; o >>= 1) {
        float om = __shfl_xor_sync(0xffffffffu, mx, o);
        float os = __shfl_xor_sync(0xffffffffu, s, o);
        float nm = fmaxf(mx, om);
        s = s * __expf(mx - nm) + os * __expf(om - nm);
        mx = nm;
    }
    if (!ln) { sm_[w] = mx; ss_[w] = s; }
    __syncthreads();
    if (tid == 0) {
        float M2 = sm_[0], S2 = ss_[0];
#pragma unroll
        for (int q = 1; q < 16; q++) {
            float nm = fmaxf(M2, sm_[q]);
            S2 = S2 * __expf(M2 - nm) + ss_[q] * __expf(sm_[q] - nm);
            M2 = nm;
        }
        fm = M2; fs = 1.f / S2;
    }
    __syncthreads();
    float MM = fm, IS = fs;
    for (int i = tid; i < N; i += 512) row[i] = __expf(row[i] - MM) * IS;
}

// ---------------- launch ----------------
extern "C" void kernel_launch(void* const* d_in, const int* in_sizes, int n_in,
                              void* d_out, int out_size)
{
    (void)in_sizes; (void)n_in; (void)out_size;
    const int*   tok = (const int*)d_in[0];
    const float* emb = (const float*)d_in[1];
    const float* W0  = (const float*)d_in[2];
    const float* U0  = (const float*)d_in[3];
    const float* b0  = (const float*)d_in[4];
    const float* W1  = (const float*)d_in[5];
    const float* U1  = (const float*)d_in[6];
    const float* b1  = (const float*)d_in[7];
    const float* W2  = (const float*)d_in[8];
    const float* U2  = (const float*)d_in[9];
    const float* b2  = (const float*)d_in[10];
    float* out = (float*)d_out;

    float* xg;
    __nv_bfloat16 *ab0, *ab1, *ab2, *ab3, *w0t, *w1t, *w2t, *embb;
    cudaGetSymbolAddress((void**)&xg, g_xg);
    cudaGetSymbolAddress((void**)&ab0, g_ab0);
    cudaGetSymbolAddress((void**)&ab1, g_ab1);
    cudaGetSymbolAddress((void**)&ab2, g_ab2);
    cudaGetSymbolAddress((void**)&ab3, g_ab3);
    cudaGetSymbolAddress((void**)&w0t, g_w0t);
    cudaGetSymbolAddress((void**)&w1t, g_w1t);
    cudaGetSymbolAddress((void**)&w2t, g_w2t);
    cudaGetSymbolAddress((void**)&embb, g_embb);

    const int SMEM_BIG   = 32 * 1160 * 2 + 16 * 1160 * 2 + 4096;   // 115456
    const int SMEM_SMALL = 32 * 408 * 2 + 16 * 408 * 2 + 4096;     // 43264
    cudaFuncSetAttribute((const void*)lstm_tc_k<NHID, 1152, 144>,
                         cudaFuncAttributeMaxDynamicSharedMemorySize, SMEM_BIG);
    cudaFuncSetAttribute((const void*)lstm_tc_k<NINP, 400, 50>,
                         cudaFuncAttributeMaxDynamicSharedMemorySize, SMEM_SMALL);
    cudaFuncSetAttribute((const void*)bf16_gemm_k<true, 1>,
                         cudaFuncAttributeMaxDynamicSharedMemorySize, GEMM_SMEM);
    cudaFuncSetAttribute((const void*)bf16_gemm_k<true, 4>,
                         cudaFuncAttributeMaxDynamicSharedMemorySize, GEMM_SMEM);
    cudaFuncSetAttribute((const void*)bf16_gemm_512_k<1>,
                         cudaFuncAttributeMaxDynamicSharedMemorySize, GEMM_SMEM);

    // barrier generation bases (prep resets g_bar once per replay)
    const unsigned B0 = 0;
    const unsigned B1 = 257u * 144u;
    const unsigned B2 = 2u * 257u * 144u;

    // 1) fused prep
    prep_k<<<PREP_BLOCKS, 256>>>(emb, W0, W1, W2);

    // 2) embedding
    embed_bf_k<<<M_TOK, 128>>>(tok, embb, ab0);

    // 3) layer 0  (K=448, streaming, KTAIL=1)
    bf16_gemm_k<true, 1><<<dim3((4 * NHID + 127) / 128, M_TOK / 128), 256, GEMM_SMEM>>>(
        ab0, w0t, b0, xg, M_TOK, 4 * NHID, KP_400);
    lstm_tc_k<NHID, 1152, 144><<<144, 256, SMEM_BIG>>>(U0, xg, ab1, KP_1150, B0);

    // 4) layer 1  (K=1152, streaming, KTAIL=4)
    bf16_gemm_k<true, 4><<<dim3((4 * NHID + 127) / 128, M_TOK / 128), 256, GEMM_SMEM>>>(
        ab1, w1t, b1, xg, M_TOK, 4 * NHID, KP_1150);
    lstm_tc_k<NHID, 1152, 144><<<144, 256, SMEM_BIG>>>(U1, xg, ab2, KP_1150, B1);

    // 5) layer 2  (K=1152, streaming, KTAIL=4)
    bf16_gemm_k<true, 4><<<dim3((4 * NINP + 127) / 128, M_TOK / 128), 256, GEMM_SMEM>>>(
        ab2, w2t, b2, xg, M_TOK, 4 * NINP, KP_1150);
    lstm_tc_k<NINP, 400, 50><<<50, 256, SMEM_SMALL>>>(U2, xg, ab3, KP_400, B2);

    // 6) tied decode: 512-thread occupancy probe (128x128 tile, 16 warps)
    bf16_gemm_512_k<1><<<dim3((VOCABP1 + 127) / 128, M_TOK / 128), 512, GEMM_SMEM>>>(
        ab3, embb, out, M_TOK, VOCABP1, KP_400);

    // 7) in-place softmax
    softmax_k<<<M_TOK, 512>>>(out, VOCABP1);
}

// round 17
// speedup vs baseline: 1.1472x; 1.1472x over previous
#include <cuda_runtime.h>
#include <cuda_bf16.h>
#include <cstdint>
#include <math.h>

#define T_SEQ   256
#define BATCH   16
#define NINP    400
#define NHID    1150
#define VOCABP1 33279
#define M_TOK   (BATCH * T_SEQ)   // 4096
#define NBLK    260               // ceil(33279/128)

#define KP_400  448
#define KP_1150 1152

// ---------------- scratch (static device globals; no allocation) ----------------
__device__ float g_xg[(size_t)M_TOK * 4 * NHID];           // gate preactivations
__device__ __nv_bfloat16 g_hb[2][16 * 1160];               // h ping-pong, [b][u], SH stride
__device__ unsigned g_bar;
__device__ float g_pmax[(size_t)M_TOK * NBLK];             // per-row-block softmax max
__device__ float g_psum[(size_t)M_TOK * NBLK];             // per-row-block sumexp

__device__ __nv_bfloat16 g_ab0[(size_t)M_TOK * KP_400];
__device__ __nv_bfloat16 g_ab1[(size_t)M_TOK * KP_1150];
__device__ __nv_bfloat16 g_ab2[(size_t)M_TOK * KP_1150];
__device__ __nv_bfloat16 g_ab3[(size_t)M_TOK * KP_400];
__device__ __nv_bfloat16 g_w0t[(size_t)4600 * KP_400];
__device__ __nv_bfloat16 g_w1t[(size_t)4600 * KP_1150];
__device__ __nv_bfloat16 g_w2t[(size_t)1600 * KP_1150];
__device__ __nv_bfloat16 g_embb[(size_t)VOCABP1 * KP_400];

// ---------------- helpers ----------------
__device__ __forceinline__ uint32_t smem_to_u32(const void* p) {
    uint32_t a;
    asm("{ .reg .u64 t; cvta.to.shared.u64 t, %1; cvt.u32.u64 %0, t; }"
        : "=r"(a) : "l"(p));
    return a;
}
#define SMEM_SWIZZLE_128B(b) ((b) ^ (((b) >> 3) & 0x70))

#define MMA_BF16(d, a, b)                                                     \
    asm volatile("mma.sync.aligned.m16n8k16.row.col.f32.bf16.bf16.f32 "      \
                 "{%0,%1,%2,%3}, {%4,%5,%6,%7}, {%8,%9}, {%0,%1,%2,%3};"      \
                 : "+f"(d[0]), "+f"(d[1]), "+f"(d[2]), "+f"(d[3])             \
                 : "r"(a[0]), "r"(a[1]), "r"(a[2]), "r"(a[3]),                \
                   "r"(b[0]), "r"(b[1]))

// online-softmax merge of a single value / a (max,sum) pair
__device__ __forceinline__ void sm_merge_val(float& mx, float& sm, float v) {
    float nm = fmaxf(mx, v);
    sm = sm * __expf(mx - nm) + __expf(v - nm);
    mx = nm;
}
__device__ __forceinline__ void sm_merge_pair(float& mx, float& sm, float om, float os) {
    float nm = fmaxf(mx, om);
    sm = sm * __expf(mx - nm) + os * __expf(om - nm);
    mx = nm;
}

// ---------------- grid barrier (monotonic across launches; prep resets) --------
__device__ __forceinline__ void grid_sync(unsigned target) {
    __syncthreads();
    if (threadIdx.x == 0) {
        __threadfence();
        atomicAdd(&g_bar, 1u);
        while (*(volatile unsigned*)&g_bar < target) {}
        __threadfence();
    }
    __syncthreads();
}

// ---------------- fused prep kernel (ONE launch; also resets g_bar) -------------
#define PREP_BLOCKS 9528

__device__ __forceinline__ void transpose_tile(
    const float* __restrict__ W, __nv_bfloat16* __restrict__ Wt,
    int K, int N, int Kpad, int bt, int nyb, float (*tile)[33])
{
    int n0 = (bt / nyb) * 32, k0 = (bt % nyb) * 32;
    int tx = threadIdx.x & 31, ty = threadIdx.x >> 5;
    for (int i = ty; i < 32; i += 8) {
        int k = k0 + i, n = n0 + tx;
        tile[i][tx] = (k < K && n < N) ? W[(size_t)k * N + n] : 0.f;
    }
    __syncthreads();
    for (int i = ty; i < 32; i += 8) {
        int n = n0 + i, k = k0 + tx;
        if (n < N && k < Kpad)
            Wt[(size_t)n * Kpad + k] = __float2bfloat16(tile[tx][i]);
    }
}

__global__ __launch_bounds__(256) void prep_k(
    const float* __restrict__ emb,
    const float* __restrict__ W0, const float* __restrict__ W1,
    const float* __restrict__ W2)
{
    __shared__ float tile[32][33];
    int b = blockIdx.x;
    if (b < 512) {
        const size_t tot = (size_t)VOCABP1 * KP_400;
        for (size_t idx = (size_t)b * 256 + threadIdx.x; idx < tot; idx += 512 * 256) {
            int r = (int)(idx / KP_400), c = (int)(idx % KP_400);
            g_embb[idx] = (c < NINP) ? __float2bfloat16(emb[(size_t)r * NINP + c])
                                     : __nv_bfloat16(0.f);
        }
    } else if (b < 2528) {
        transpose_tile(W0, g_w0t, NINP, 4 * NHID, KP_400, b - 512, 14, tile);
    } else if (b < 7712) {
        transpose_tile(W1, g_w1t, NHID, 4 * NHID, KP_1150, b - 2528, 36, tile);
    } else if (b < 9512) {
        transpose_tile(W2, g_w2t, NHID, 4 * NINP, KP_1150, b - 7712, 36, tile);
    } else {
        if (b == 9512 && threadIdx.x == 0) g_bar = 0u;   // barrier reset, once/replay
        int m = (b - 9512) * 256 + threadIdx.x;
        if (m < M_TOK) {
            g_ab1[(size_t)m * KP_1150 + 1150] = __nv_bfloat16(0.f);
            g_ab1[(size_t)m * KP_1150 + 1151] = __nv_bfloat16(0.f);
            g_ab2[(size_t)m * KP_1150 + 1150] = __nv_bfloat16(0.f);
            g_ab2[(size_t)m * KP_1150 + 1151] = __nv_bfloat16(0.f);
            for (int c = NINP; c < KP_400; c++)
                g_ab3[(size_t)m * KP_400 + c] = __nv_bfloat16(0.f);
        }
    }
}

// embedding gather in bf16
__global__ void embed_bf_k(const int* __restrict__ tok,
                           const __nv_bfloat16* __restrict__ embb,
                           __nv_bfloat16* __restrict__ x0) {
    int m = blockIdx.x;
    int t = tok[m];
    const uint4* src = (const uint4*)(embb + (size_t)t * KP_400);
    uint4* dst = (uint4*)(x0 + (size_t)m * KP_400);
    for (int i = threadIdx.x; i < KP_400 * 2 / 16; i += blockDim.x) dst[i] = src[i];
}

// ================= streaming bf16 GEMM, 128x128 tile, 256 thr ===================
// STATS: also emit per-(row, n-block) online-softmax (max, sumexp) to g_pmax/g_psum.
#define GSTAGES 3
#define GEMM_SMEM (GSTAGES * 32768)

template<bool BIAS, int KTAIL, bool STATS>
__global__ __launch_bounds__(256, 2) void bf16_gemm_k(
    const __nv_bfloat16* __restrict__ A, const __nv_bfloat16* __restrict__ B,
    const float* __restrict__ bias, float* __restrict__ C,
    int M, int N, int Kpad)
{
    extern __shared__ char smem[];
    const uint32_t sbase = smem_to_u32(smem);

    const int tid  = threadIdx.x;
    const int wid  = tid >> 5;
    const int lane = tid & 31;
    const int bm   = blockIdx.y * 128;
    const int bn   = blockIdx.x * 128;
    const int wm   = (wid >> 2) * 64;
    const int wn   = (wid & 3) * 32;

    const int lrow  = tid >> 1;
    const int lhalf = tid & 1;
    const __nv_bfloat16* Asrc = A + (size_t)(bm + lrow) * Kpad + lhalf * 32;
    const int gnrow = bn + lrow;
    const __nv_bfloat16* Bsrc = B + (size_t)gnrow * Kpad + lhalf * 32;
    const int bvalid = (gnrow < N) ? 16 : 0;

    const int lm16 = lane & 15;
    const int lk16 = lane >> 4;
    const int ln8  = lane & 7;
    const int lkb  = (lane >> 3) & 1;

    float acc[4][4][4];
#pragma unroll
    for (int mf = 0; mf < 4; mf++)
#pragma unroll
        for (int nf = 0; nf < 4; nf++)
#pragma unroll
            for (int i = 0; i < 4; i++) acc[mf][nf][i] = 0.f;

    auto load_tile = [&](int stage, int kt) {
        uint32_t sa = sbase + stage * 32768;
        uint32_t sb = sa + 16384;
        const __nv_bfloat16* ap = Asrc + kt * 64;
        const __nv_bfloat16* bp = Bsrc + kt * 64;
#pragma unroll
        for (int j = 0; j < 4; j++) {
            uint32_t off = SMEM_SWIZZLE_128B((uint32_t)(lrow * 128 + lhalf * 64 + j * 16));
            asm volatile("cp.async.cg.shared.global [%0], [%1], 16;"
                         :: "r"(sa + off), "l"(ap + j * 8));
            asm volatile("cp.async.cg.shared.global [%0], [%1], 16, %2;"
                         :: "r"(sb + off), "l"(bp + j * 8), "r"(bvalid));
        }
    };

    const int nkt = Kpad >> 6;

#pragma unroll
    for (int s = 0; s < GSTAGES - 1; s++) {
        load_tile(s, s);
        asm volatile("cp.async.commit_group;" ::: "memory");
    }

    for (int kt = 0; kt < nkt; kt++) {
        asm volatile("cp.async.wait_group %0;" :: "n"(GSTAGES - 2) : "memory");
        __syncthreads();

        if (kt + GSTAGES - 1 < nkt) {
            load_tile((kt + GSTAGES - 1) % GSTAGES, kt + GSTAGES - 1);
            asm volatile("cp.async.commit_group;" ::: "memory");
        } else {
            asm volatile("cp.async.commit_group;" ::: "memory");
        }

        uint32_t sa = sbase + (kt % GSTAGES) * 32768;
        uint32_t sb = sa + 16384;
        const bool last = (kt == nkt - 1);
#pragma unroll
        for (int s = 0; s < 4; s++) {
            if (s >= KTAIL && last) break;
            uint32_t af[4][4], bfr[4][2];
#pragma unroll
            for (int mf = 0; mf < 4; mf++) {
                uint32_t off = (uint32_t)((wm + mf * 16 + lm16) * 128 + s * 32 + lk16 * 16);
                asm volatile("ldmatrix.sync.aligned.m8n8.x4.shared.b16 "
                             "{%0,%1,%2,%3}, [%4];"
                             : "=r"(af[mf][0]), "=r"(af[mf][1]),
                               "=r"(af[mf][2]), "=r"(af[mf][3])
                             : "r"(sa + SMEM_SWIZZLE_128B(off)));
            }
#pragma unroll
            for (int nf = 0; nf < 4; nf++) {
                uint32_t off = (uint32_t)((wn + nf * 8 + ln8) * 128 + s * 32 + lkb * 16);
                asm volatile("ldmatrix.sync.aligned.m8n8.x2.shared.b16 "
                             "{%0,%1}, [%2];"
                             : "=r"(bfr[nf][0]), "=r"(bfr[nf][1])
                             : "r"(sb + SMEM_SWIZZLE_128B(off)));
            }
#pragma unroll
            for (int mf = 0; mf < 4; mf++)
#pragma unroll
                for (int nf = 0; nf < 4; nf++)
                    MMA_BF16(acc[mf][nf], af[mf], bfr[nf]);
        }
    }

    const int gID = lane >> 2;
    const int tg  = lane & 3;
#pragma unroll
    for (int mf = 0; mf < 4; mf++) {
        int r0 = bm + wm + mf * 16 + gID;
#pragma unroll
        for (int nf = 0; nf < 4; nf++) {
            int c0 = bn + wn + nf * 8 + tg * 2;
            float b0v = 0.f, b1v = 0.f;
            if (BIAS) {
                if (c0 < N)     b0v = bias[c0];
                if (c0 + 1 < N) b1v = bias[c0 + 1];
            }
            if (c0 < N) {
                C[(size_t)r0 * N + c0]       = acc[mf][nf][0] + b0v;
                C[(size_t)(r0 + 8) * N + c0] = acc[mf][nf][2] + b0v;
            }
            if (c0 + 1 < N) {
                C[(size_t)r0 * N + c0 + 1]       = acc[mf][nf][1] + b1v;
                C[(size_t)(r0 + 8) * N + c0 + 1] = acc[mf][nf][3] + b1v;
            }
        }
    }

    if (STATS) {
        // per-(row, 128-col block) online-softmax stats
        __syncthreads();                         // stage smem free for reuse
        float* s_mx = (float*)smem;              // [128 rows][4 wn]
        float* s_sm = s_mx + 512;
        const int mgrp = wid >> 2;
        const int wnid = wid & 3;
#pragma unroll
        for (int mf = 0; mf < 4; mf++) {
#pragma unroll
            for (int which = 0; which < 2; which++) {
                float mx = -3.4e38f, sm = 0.f;
#pragma unroll
                for (int nf = 0; nf < 4; nf++) {
                    int c0 = bn + wn + nf * 8 + tg * 2;
                    if (c0 < N)     sm_merge_val(mx, sm, acc[mf][nf][which * 2 + 0]);
                    if (c0 + 1 < N) sm_merge_val(mx, sm, acc[mf][nf][which * 2 + 1]);
                }
#pragma unroll
                for (int o = 1; o <= 2; o <<= 1) {
                    float om = __shfl_xor_sync(0xffffffffu, mx, o);
                    float os = __shfl_xor_sync(0xffffffffu, sm, o);
                    sm_merge_pair(mx, sm, om, os);
                }
                if (tg == 0) {
                    int rloc = mgrp * 64 + mf * 16 + gID + which * 8;
                    s_mx[rloc * 4 + wnid] = mx;
                    s_sm[rloc * 4 + wnid] = sm;
                }
            }
        }
        __syncthreads();
        if (tid < 128) {
            float mx = -3.4e38f, sm = 0.f;
#pragma unroll
            for (int w = 0; w < 4; w++)
                sm_merge_pair(mx, sm, s_mx[tid * 4 + w], s_sm[tid * 4 + w]);
            int gm = bm + tid;
            g_pmax[(size_t)gm * NBLK + blockIdx.x] = mx;
            g_psum[(size_t)gm * NBLK + blockIdx.x] = sm;
        }
    }
}

// ============== tensor-core persistent LSTM recurrence (bar_base arg) ===========
template<int U, int KPU, int NCTA>
__global__ __launch_bounds__(256) void lstm_tc_k(
    const float* __restrict__ Um,
    const float* __restrict__ xg,
    __nv_bfloat16* __restrict__ xout,
    int ostride, unsigned bar_base)
{
    constexpr int N4 = 4 * U;
    constexpr int KT = KPU / 16;
    constexpr int SH = KPU + 8;

    extern __shared__ char smraw[];
    const uint32_t ubase = smem_to_u32(smraw);
    const uint32_t hbase = ubase + 32 * SH * 2;
    float* red = (float*)(smraw + 32 * SH * 2 + 16 * SH * 2);
    float* gat = red + 512;
    __nv_bfloat16* U_s = (__nv_bfloat16*)smraw;

    const int tid  = threadIdx.x;
    const int wid  = tid >> 5;
    const int lane = tid & 31;
    const int nt   = wid & 3;
    const int kh   = wid >> 2;
    const int lm16 = lane & 15;
    const int lk16 = lane >> 4;
    const int ln8  = lane & 7;
    const int lkb  = (lane >> 3) & 1;
    const int gID  = lane >> 2;
    const int tg   = lane & 3;
    const int ub   = blockIdx.x * 8;

    for (int idx = tid; idx < 32 * KPU; idx += 256) {
        int k = idx >> 5, cc = idx & 31;
        int g = cc >> 3, ul = cc & 7;
        int uu = ub + ul;
        float v = (k < U && uu < U) ? Um[(size_t)k * N4 + (size_t)g * U + uu] : 0.f;
        U_s[cc * SH + k] = __float2bfloat16(v);
    }
    for (int idx = blockIdx.x * 256 + tid; idx < 2 * 16 * SH; idx += NCTA * 256)
        ((__nv_bfloat16*)g_hb)[idx] = __nv_bfloat16(0.f);

    float creg = 0.f;
    unsigned gen = 1;
    grid_sync(bar_base + gen * NCTA);

    const uint32_t aaddr0 = hbase + lm16 * (SH * 2) + lk16 * 16;
    const uint32_t baddr0 = ubase + (nt * 8 + ln8) * (SH * 2) + lkb * 16;
    const int uu0 = ub + tg * 2, uu1 = uu0 + 1;

    for (int t = 0; t < T_SEQ; ++t) {
        // issue h stage (cp.async), then prefetch xg under the wait
        {
            const char* src = (const char*)&g_hb[t & 1][0];
            for (int i = tid; i < 2 * SH; i += 256) {
                asm volatile("cp.async.cg.shared.global [%0], [%1], 16;"
                             :: "r"(hbase + i * 16), "l"(src + i * 16));
            }
            asm volatile("cp.async.commit_group;" ::: "memory");
        }

        float xv0 = 0.f, xv1 = 0.f, xv2 = 0.f, xv3 = 0.f;
        if (kh == 0) {
            const float* xr0 = xg + ((size_t)gID * T_SEQ + t) * N4 + (size_t)nt * U;
            const float* xr1 = xg + ((size_t)(gID + 8) * T_SEQ + t) * N4 + (size_t)nt * U;
            if (uu0 < U) { xv0 = __ldg(&xr0[uu0]); xv2 = __ldg(&xr1[uu0]); }
            if (uu1 < U) { xv1 = __ldg(&xr0[uu1]); xv3 = __ldg(&xr1[uu1]); }
        }

        asm volatile("cp.async.wait_group 0;" ::: "memory");
        __syncthreads();

        float accA[4] = {0.f, 0.f, 0.f, 0.f};
        float accB[4] = {0.f, 0.f, 0.f, 0.f};
#pragma unroll
        for (int kt = kh; kt < KT; kt += 2) {
            uint32_t a[4], b[2];
            asm volatile("ldmatrix.sync.aligned.m8n8.x4.shared.b16 "
                         "{%0,%1,%2,%3}, [%4];"
                         : "=r"(a[0]), "=r"(a[1]), "=r"(a[2]), "=r"(a[3])
                         : "r"(aaddr0 + kt * 32));
            asm volatile("ldmatrix.sync.aligned.m8n8.x2.shared.b16 "
                         "{%0,%1}, [%2];"
                         : "=r"(b[0]), "=r"(b[1])
                         : "r"(baddr0 + kt * 32));
            if ((kt >> 1) & 1) { MMA_BF16(accB, a, b); }
            else               { MMA_BF16(accA, a, b); }
        }
#pragma unroll
        for (int i = 0; i < 4; i++) accA[i] += accB[i];

        const int i00 = nt * 128 + gID * 8 + tg * 2;
        const int i10 = nt * 128 + (gID + 8) * 8 + tg * 2;
        if (kh == 1) {
            red[i00]     = accA[0];
            red[i00 + 1] = accA[1];
            red[i10]     = accA[2];
            red[i10 + 1] = accA[3];
        }
        __syncthreads();
        if (kh == 0) {
            accA[0] += red[i00]     + xv0;
            accA[1] += red[i00 + 1] + xv1;
            accA[2] += red[i10]     + xv2;
            accA[3] += red[i10 + 1] + xv3;
            gat[i00]     = accA[0];
            gat[i00 + 1] = accA[1];
            gat[i10]     = accA[2];
            gat[i10 + 1] = accA[3];
        }
        __syncthreads();

        if (tid < 128) {
            int b = tid >> 3, ul = tid & 7;
            int uu = ub + ul;
            float iv  = gat[0 * 128 + tid];
            float fv  = gat[1 * 128 + tid];
            float cgv = gat[2 * 128 + tid];
            float ov  = gat[3 * 128 + tid];
            iv = 1.f / (1.f + __expf(-iv));
            fv = 1.f / (1.f + __expf(-fv));
            ov = 1.f / (1.f + __expf(-ov));
            cgv = tanhf(cgv);
            creg = fv * creg + iv * cgv;
            float hv = ov * tanhf(creg);
            if (uu < U) {
                __nv_bfloat16 hb = __float2bfloat16(hv);
                g_hb[(t & 1) ^ 1][b * SH + uu] = hb;
                xout[((size_t)b * T_SEQ + t) * ostride + uu] = hb;
            }
        }
        gen++;
        grid_sync(bar_base + gen * NCTA);   // syncthreads + fence + arrive
    }
}

// ---------------- normalize: merge block stats, one read+write pass -------------
__global__ __launch_bounds__(512) void norm_k(float* __restrict__ out, int N) {
    int m = blockIdx.x;
    float* row = out + (size_t)m * N;
    const float* pm = g_pmax + (size_t)m * NBLK;
    const float* ps = g_psum + (size_t)m * NBLK;
    __shared__ float sm_[16], ss_[16];
    __shared__ float fm, fs;
    int tid = threadIdx.x, w = tid >> 5, ln = tid & 31;

    float mx = -3.4e38f, s = 0.f;
    for (int i = tid; i < NBLK; i += 512)
        sm_merge_pair(mx, s, pm[i], ps[i]);
#pragma unroll
    for (int o = 16; o; o >>= 1) {
        float om = __shfl_xor_sync(0xffffffffu, mx, o);
        float os = __shfl_xor_sync(0xffffffffu, s, o);
        sm_merge_pair(mx, s, om, os);
    }
    if (!ln) { sm_[w] = mx; ss_[w] = s; }
    __syncthreads();
    if (tid == 0) {
        float M2 = sm_[0], S2 = ss_[0];
#pragma unroll
        for (int q = 1; q < 16; q++) sm_merge_pair(M2, S2, sm_[q], ss_[q]);
        fm = M2; fs = 1.f / S2;
    }
    __syncthreads();
    float MM = fm, IS = fs;
    for (int i = tid; i < N; i += 512) row[i] = __expf(row[i] - MM) * IS;
}

// ---------------- launch ----------------
extern "C" void kernel_launch(void* const* d_in, const int* in_sizes, int n_in,
                              void* d_out, int out_size)
{
    (void)in_sizes; (void)n_in; (void)out_size;
    const int*   tok = (const int*)d_in[0];
    const float* emb = (const float*)d_in[1];
    const float* W0  = (const float*)d_in[2];
    const float* U0  = (const float*)d_in[3];
    const float* b0  = (const float*)d_in[4];
    const float* W1  = (const float*)d_in[5];
    const float* U1  = (const float*)d_in[6];
    const float* b1  = (const float*)d_in[7];
    const float* W2  = (const float*)d_in[8];
    const float* U2  = (const float*)d_in[9];
    const float* b2  = (const float*)d_in[10];
    float* out = (float*)d_out;

    float* xg;
    __nv_bfloat16 *ab0, *ab1, *ab2, *ab3, *w0t, *w1t, *w2t, *embb;
    cudaGetSymbolAddress((void**)&xg, g_xg);
    cudaGetSymbolAddress((void**)&ab0, g_ab0);
    cudaGetSymbolAddress((void**)&ab1, g_ab1);
    cudaGetSymbolAddress((void**)&ab2, g_ab2);
    cudaGetSymbolAddress((void**)&ab3, g_ab3);
    cudaGetSymbolAddress((void**)&w0t, g_w0t);
    cudaGetSymbolAddress((void**)&w1t, g_w1t);
    cudaGetSymbolAddress((void**)&w2t, g_w2t);
    cudaGetSymbolAddress((void**)&embb, g_embb);

    const int SMEM_BIG   = 32 * 1160 * 2 + 16 * 1160 * 2 + 4096;   // 115456
    const int SMEM_SMALL = 32 * 408 * 2 + 16 * 408 * 2 + 4096;     // 43264
    cudaFuncSetAttribute((const void*)lstm_tc_k<NHID, 1152, 144>,
                         cudaFuncAttributeMaxDynamicSharedMemorySize, SMEM_BIG);
    cudaFuncSetAttribute((const void*)lstm_tc_k<NINP, 400, 50>,
                         cudaFuncAttributeMaxDynamicSharedMemorySize, SMEM_SMALL);
    cudaFuncSetAttribute((const void*)bf16_gemm_k<true, 1, false>,
                         cudaFuncAttributeMaxDynamicSharedMemorySize, GEMM_SMEM);
    cudaFuncSetAttribute((const void*)bf16_gemm_k<true, 4, false>,
                         cudaFuncAttributeMaxDynamicSharedMemorySize, GEMM_SMEM);
    cudaFuncSetAttribute((const void*)bf16_gemm_k<false, 1, true>,
                         cudaFuncAttributeMaxDynamicSharedMemorySize, GEMM_SMEM);

    // barrier generation bases (prep resets g_bar once per replay)
    const unsigned B0 = 0;
    const unsigned B1 = 257u * 144u;
    const unsigned B2 = 2u * 257u * 144u;

    // 1) fused prep
    prep_k<<<PREP_BLOCKS, 256>>>(emb, W0, W1, W2);

    // 2) embedding
    embed_bf_k<<<M_TOK, 128>>>(tok, embb, ab0);

    // 3) layer 0  (K=448, streaming, KTAIL=1)
    bf16_gemm_k<true, 1, false><<<dim3((4 * NHID + 127) / 128, M_TOK / 128), 256, GEMM_SMEM>>>(
        ab0, w0t, b0, xg, M_TOK, 4 * NHID, KP_400);
    lstm_tc_k<NHID, 1152, 144><<<144, 256, SMEM_BIG>>>(U0, xg, ab1, KP_1150, B0);

    // 4) layer 1  (K=1152, streaming, KTAIL=4)
    bf16_gemm_k<true, 4, false><<<dim3((4 * NHID + 127) / 128, M_TOK / 128), 256, GEMM_SMEM>>>(
        ab1, w1t, b1, xg, M_TOK, 4 * NHID, KP_1150);
    lstm_tc_k<NHID, 1152, 144><<<144, 256, SMEM_BIG>>>(U1, xg, ab2, KP_1150, B1);

    // 5) layer 2  (K=1152, streaming, KTAIL=4)
    bf16_gemm_k<true, 4, false><<<dim3((4 * NINP + 127) / 128, M_TOK / 128), 256, GEMM_SMEM>>>(
        ab2, w2t, b2, xg, M_TOK, 4 * NINP, KP_1150);
    lstm_tc_k<NINP, 400, 50><<<50, 256, SMEM_SMALL>>>(U2, xg, ab3, KP_400, B2);

    // 6) tied decode with fused softmax stats, straight into d_out
    bf16_gemm_k<false, 1, true><<<dim3(NBLK, M_TOK / 128), 256, GEMM_SMEM>>>(
        ab3, embb, nullptr, out, M_TOK, VOCABP1, KP_400);

    // 7) normalize (single read+write pass)
    norm_k<<<M_TOK, 512>>>(out, VOCABP1);
}